// round 14
// baseline (speedup 1.0000x reference)
#include <cuda_runtime.h>

#define BB 8
#define HH 1024
#define WW 1024
#define NT 256

// ---- NCC: float4-per-lane, TWO independent 16-row slide chains per task ----
#define OUTW 120
#define NSTRIP 9
#define SEG 16                           // rows per chain
#define V2SEG 32                         // 32 pair-segments of 32 rows
#define NCC_TASKS (NSTRIP * V2SEG * BB)  // 2304

// ---- smoothness warp tasks: 8-row full-width strips ----
#define SM_TASKS 2048                    // 16 planes x 128 strips
#define NTASKS (NCC_TASKS + SM_TASKS)    // 4352

#define GRID_BLOCKS 444                  // 3/SM x 148 SMs

typedef unsigned long long u64;

__device__ double g_acc[3] = {0.0, 0.0, 0.0};
__device__ unsigned int g_ticket = 0;
__device__ unsigned int g_count = 0;

__device__ __forceinline__ float frcp(float x) {
    float r; asm("rcp.approx.ftz.f32 %0, %1;" : "=f"(r) : "f"(x)); return r;
}
__device__ __forceinline__ u64 PK2(float lo, float hi) {
    u64 r; asm("mov.b64 %0, {%1, %2};" : "=l"(r) : "f"(lo), "f"(hi)); return r;
}
__device__ __forceinline__ void UPK2(u64 v, float& lo, float& hi) {
    asm("mov.b64 {%0, %1}, %2;" : "=f"(lo), "=f"(hi) : "l"(v));
}
__device__ __forceinline__ u64 ADD2(u64 a, u64 b) {
    u64 r; asm("add.rn.f32x2 %0, %1, %2;" : "=l"(r) : "l"(a), "l"(b)); return r;
}
__device__ __forceinline__ u64 MUL2(u64 a, u64 b) {
    u64 r; asm("mul.rn.f32x2 %0, %1, %2;" : "=l"(r) : "l"(a), "l"(b)); return r;
}
__device__ __forceinline__ u64 FMA2(u64 a, u64 b, u64 c) {
    u64 r; asm("fma.rn.f32x2 %0, %1, %2, %3;" : "=l"(r) : "l"(a), "l"(b), "l"(c)); return r;
}

// Horizontal 9-tap window sums for a lane owning cols rb..rb+3.
// All 8 shuffles independent (depth-1). Valid for lanes 1..30.
__device__ __forceinline__ void hwin4(float v0, float v1, float v2, float v3,
                                      float& W0, float& W1, float& W2, float& W3) {
    const unsigned m = 0xffffffffu;
    float p2 = v0 + v1;
    float s2 = v2 + v3;
    float Q  = p2 + s2;
    float p3 = p2 + v2;
    float s3 = s2 + v1;
    float Qm  = __shfl_up_sync(m, Q, 1);
    float s3m = __shfl_up_sync(m, s3, 1);
    float s2m = __shfl_up_sync(m, s2, 1);
    float s1m = __shfl_up_sync(m, v3, 1);
    float p1p = __shfl_down_sync(m, v0, 1);
    float p2p = __shfl_down_sync(m, p2, 1);
    float p3p = __shfl_down_sync(m, p3, 1);
    float Qp  = __shfl_down_sync(m, Q, 1);
    W0 = Qm  + Q + p1p;
    W1 = s3m + Q + p2p;
    W2 = s2m + Q + p3p;
    W3 = s1m + Q + Qp;
}

template<bool MASKED, bool YCLEAN>
__device__ __forceinline__ float ncc_task_pair(const float4* __restrict__ Ip,
                                               const float4* __restrict__ Jp,
                                               int y0, u64 cm01, u64 cm23,
                                               bool m0, bool m1, bool m2, bool m3)
{
    const int RS = WW / 4;
    const float4 z4 = make_float4(0.f, 0.f, 0.f, 0.f);
    const u64 NEG1   = PK2(-1.0f, -1.0f);
    const u64 NINV81 = PK2(-1.0f / 81.0f, -1.0f / 81.0f);
    const u64 EPS2   = PK2(1e-9f, 1e-9f);

    // two independent chains: c=0 rows [y0, y0+16), c=1 rows [y0+16, y0+32)
    u64 sI01[2]={0,0}, sI23[2]={0,0}, sJ01[2]={0,0}, sJ23[2]={0,0};
    u64 sII01[2]={0,0}, sII23[2]={0,0}, sJJ01[2]={0,0}, sJJ23[2]={0,0};
    u64 sIJ01[2]={0,0}, sIJ23[2]={0,0};

    // prefill each chain with rows yc-5 .. yc+3  (invariant: sums = y-5..y+3 at loop top)
    #pragma unroll
    for (int c = 0; c < 2; c++) {
        #pragma unroll
        for (int k = 0; k < 9; k++) {
            const int y = y0 + 16 * c - 5 + k;
            const bool ok = YCLEAN || (y >= 0);
            float4 vi = ok ? Ip[(long)y * RS] : z4;
            float4 vj = ok ? Jp[(long)y * RS] : z4;
            u64 i01 = PK2(vi.x, vi.y), i23 = PK2(vi.z, vi.w);
            u64 j01 = PK2(vj.x, vj.y), j23 = PK2(vj.z, vj.w);
            if (MASKED) {
                i01 = MUL2(i01, cm01); i23 = MUL2(i23, cm23);
                j01 = MUL2(j01, cm01); j23 = MUL2(j23, cm23);
            }
            sI01[c] = ADD2(sI01[c], i01);   sI23[c] = ADD2(sI23[c], i23);
            sJ01[c] = ADD2(sJ01[c], j01);   sJ23[c] = ADD2(sJ23[c], j23);
            sII01[c] = FMA2(i01, i01, sII01[c]); sII23[c] = FMA2(i23, i23, sII23[c]);
            sJJ01[c] = FMA2(j01, j01, sJJ01[c]); sJJ23[c] = FMA2(j23, j23, sJJ23[c]);
            sIJ01[c] = FMA2(i01, j01, sIJ01[c]); sIJ23[c] = FMA2(i23, j23, sIJ23[c]);
        }
    }

    const float4* pIn = Ip + (long)(y0 + 4) * RS;   // chain-0 new-row base (y0+4)
    const float4* pJn = Jp + (long)(y0 + 4) * RS;
    const int ylim = HH - 4 - y0;                   // chain c new row ok iff 16c+u < ylim

    float ccSum = 0.f;

    #pragma unroll 2
    for (int u = 0; u < SEG; u++) {
        #pragma unroll
        for (int c = 0; c < 2; c++) {
            const int no = 16 * c + u;       // new-row offset from pIn
            const int oo = 16 * c + u - 9;   // old-row offset from pIn (row yc+u-5)
            float4 vN_i, vN_j, vO_i, vO_j;
            if (YCLEAN) {
                vN_i = pIn[(long)no * RS];
                vN_j = pJn[(long)no * RS];
                vO_i = pIn[(long)oo * RS];
                vO_j = pJn[(long)oo * RS];
            } else {
                const bool okn = no < ylim;
                const bool oko = (c == 1) || ((y0 + u - 5) >= 0);
                vN_i = okn ? pIn[(long)no * RS] : z4;
                vN_j = okn ? pJn[(long)no * RS] : z4;
                vO_i = oko ? pIn[(long)oo * RS] : z4;
                vO_j = oko ? pJn[(long)oo * RS] : z4;
            }
            u64 iN01 = PK2(vN_i.x, vN_i.y), iN23 = PK2(vN_i.z, vN_i.w);
            u64 jN01 = PK2(vN_j.x, vN_j.y), jN23 = PK2(vN_j.z, vN_j.w);
            u64 iO01 = PK2(vO_i.x, vO_i.y), iO23 = PK2(vO_i.z, vO_i.w);
            u64 jO01 = PK2(vO_j.x, vO_j.y), jO23 = PK2(vO_j.z, vO_j.w);
            if (MASKED) {
                iN01 = MUL2(iN01, cm01); iN23 = MUL2(iN23, cm23);
                jN01 = MUL2(jN01, cm01); jN23 = MUL2(jN23, cm23);
                iO01 = MUL2(iO01, cm01); iO23 = MUL2(iO23, cm23);
                jO01 = MUL2(jO01, cm01); jO23 = MUL2(jO23, cm23);
            }

            // combined slide: +row(y+4) -row(y-5)  => window rows y-4..y+4
            u64 dI01 = FMA2(iO01, NEG1, iN01), dI23 = FMA2(iO23, NEG1, iN23);
            u64 dJ01 = FMA2(jO01, NEG1, jN01), dJ23 = FMA2(jO23, NEG1, jN23);
            u64 eI01 = ADD2(iN01, iO01),       eI23 = ADD2(iN23, iO23);
            u64 eJ01 = ADD2(jN01, jO01),       eJ23 = ADD2(jN23, jO23);
            sI01[c] = ADD2(sI01[c], dI01);  sI23[c] = ADD2(sI23[c], dI23);
            sJ01[c] = ADD2(sJ01[c], dJ01);  sJ23[c] = ADD2(sJ23[c], dJ23);
            sII01[c] = FMA2(dI01, eI01, sII01[c]); sII23[c] = FMA2(dI23, eI23, sII23[c]);
            sJJ01[c] = FMA2(dJ01, eJ01, sJJ01[c]); sJJ23[c] = FMA2(dJ23, eJ23, sJJ23[c]);
            sIJ01[c] = FMA2(dI01, jN01, sIJ01[c]); sIJ01[c] = FMA2(iO01, dJ01, sIJ01[c]);
            sIJ23[c] = FMA2(dI23, jN23, sIJ23[c]); sIJ23[c] = FMA2(iO23, dJ23, sIJ23[c]);

            // unpack vertical sums for the shuffle-based horizontal pass
            float aI0,aI1,aI2,aI3, aJ0,aJ1,aJ2,aJ3;
            float aII0,aII1,aII2,aII3, aJJ0,aJJ1,aJJ2,aJJ3, aIJ0,aIJ1,aIJ2,aIJ3;
            UPK2(sI01[c],  aI0,  aI1);  UPK2(sI23[c],  aI2,  aI3);
            UPK2(sJ01[c],  aJ0,  aJ1);  UPK2(sJ23[c],  aJ2,  aJ3);
            UPK2(sII01[c], aII0, aII1); UPK2(sII23[c], aII2, aII3);
            UPK2(sJJ01[c], aJJ0, aJJ1); UPK2(sJJ23[c], aJJ2, aJJ3);
            UPK2(sIJ01[c], aIJ0, aIJ1); UPK2(sIJ23[c], aIJ2, aIJ3);

            float TI0,TI1,TI2,TI3, TJ0,TJ1,TJ2,TJ3;
            float TII0,TII1,TII2,TII3, TJJ0,TJJ1,TJJ2,TJJ3, TIJ0,TIJ1,TIJ2,TIJ3;
            hwin4(aI0,  aI1,  aI2,  aI3,  TI0,  TI1,  TI2,  TI3);
            hwin4(aJ0,  aJ1,  aJ2,  aJ3,  TJ0,  TJ1,  TJ2,  TJ3);
            hwin4(aII0, aII1, aII2, aII3, TII0, TII1, TII2, TII3);
            hwin4(aJJ0, aJJ1, aJJ2, aJJ3, TJJ0, TJJ1, TJJ2, TJJ3);
            hwin4(aIJ0, aIJ1, aIJ2, aIJ3, TIJ0, TIJ1, TIJ2, TIJ3);

            // packed cc epilogue for column pairs (0,1) and (2,3)
            {
                u64 TI = PK2(TI0, TI1), TJ = PK2(TJ0, TJ1);
                u64 t  = MUL2(TI, NINV81);
                u64 cr = FMA2(t, TJ, PK2(TIJ0, TIJ1));
                u64 iv = FMA2(t, TI, PK2(TII0, TII1));
                u64 q  = MUL2(TJ, NINV81);
                u64 jv = FMA2(q, TJ, PK2(TJJ0, TJJ1));
                u64 den = FMA2(iv, jv, EPS2);
                u64 c2  = MUL2(cr, cr);
                float d0, d1, n0, n1;
                UPK2(den, d0, d1); UPK2(c2, n0, n1);
                if (m0) ccSum += n0 * frcp(d0);
                if (m1) ccSum += n1 * frcp(d1);
            }
            {
                u64 TI = PK2(TI2, TI3), TJ = PK2(TJ2, TJ3);
                u64 t  = MUL2(TI, NINV81);
                u64 cr = FMA2(t, TJ, PK2(TIJ2, TIJ3));
                u64 iv = FMA2(t, TI, PK2(TII2, TII3));
                u64 q  = MUL2(TJ, NINV81);
                u64 jv = FMA2(q, TJ, PK2(TJJ2, TJJ3));
                u64 den = FMA2(iv, jv, EPS2);
                u64 c2  = MUL2(cr, cr);
                float d0, d1, n0, n1;
                UPK2(den, d0, d1); UPK2(c2, n0, n1);
                if (m2) ccSum += n0 * frcp(d0);
                if (m3) ccSum += n1 * frcp(d1);
            }
        }
    }
    return ccSum;
}

__global__ __launch_bounds__(NT, 3)
void fused_kernel(const float* __restrict__ I,
                  const float* __restrict__ J,
                  const float* __restrict__ S,
                  float* __restrict__ out)
{
    __shared__ float red[3][NT / 32];
    const int tid  = threadIdx.x;
    const int lane = tid & 31;
    const unsigned full = 0xffffffffu;

    float acc0 = 0.f, acc1 = 0.f, acc2 = 0.f;

    for (;;) {
        unsigned t;
        if (lane == 0) t = atomicAdd(&g_ticket, 1u);
        t = __shfl_sync(full, t, 0);
        if (t >= NTASKS) break;

        if (t < NCC_TASKS) {
            // v2 varies fastest -> adjacent tickets share halo rows (L2 locality)
            const int v2 = t % V2SEG;
            const int rr = t / V2SEG;
            const int s  = rr % NSTRIP;
            const int b  = rr / NSTRIP;

            const int rb = s * OUTW - 4 + 4 * lane;
            int rbc = rb < 0 ? 0 : (rb > (WW - 4) ? (WW - 4) : rb);

            const float4* Ip = (const float4*)(I + (size_t)b * HH * WW + rbc);
            const float4* Jp = (const float4*)(J + (size_t)b * HH * WW + rbc);

            const float c0 = ((unsigned)(rb + 0) < (unsigned)WW) ? 1.f : 0.f;
            const float c1 = ((unsigned)(rb + 1) < (unsigned)WW) ? 1.f : 0.f;
            const float c2 = ((unsigned)(rb + 2) < (unsigned)WW) ? 1.f : 0.f;
            const float c3 = ((unsigned)(rb + 3) < (unsigned)WW) ? 1.f : 0.f;
            const u64 cm01 = PK2(c0, c1);
            const u64 cm23 = PK2(c2, c3);

            const bool lmid = (lane >= 1) && (lane <= 30);
            const bool m0 = lmid && (rb + 0 < WW);
            const bool m1 = lmid && (rb + 1 < WW);
            const bool m2 = lmid && (rb + 2 < WW);
            const bool m3 = lmid && (rb + 3 < WW);
            const int y0 = v2 * 32;

            const bool colclean = __all_sync(full, (unsigned)rb < (unsigned)(WW - 3));
            const bool yclean   = (y0 >= 5) && (y0 + 32 + 4 <= HH);

            if (colclean) {
                acc0 += yclean ? ncc_task_pair<false, true >(Ip, Jp, y0, cm01, cm23, m0, m1, m2, m3)
                               : ncc_task_pair<false, false>(Ip, Jp, y0, cm01, cm23, m0, m1, m2, m3);
            } else {
                acc0 += yclean ? ncc_task_pair<true,  true >(Ip, Jp, y0, cm01, cm23, m0, m1, m2, m3)
                               : ncc_task_pair<true,  false>(Ip, Jp, y0, cm01, cm23, m0, m1, m2, m3);
            }
        } else {
            // ------------- smoothness: 8-row strip -------------
            const unsigned n = t - NCC_TASKS;
            const int plane = n >> 7;
            const int strip = n & 127;
            const float*  spf = S + (size_t)plane * HH * WW;
            const float4* sp4 = (const float4*)spf;
            const int y0 = strip * 8;

            #pragma unroll 1
            for (int p = 0; p < 8; p++) {
                const int cidx = p * 32 + lane;
                float4 cur = sp4[(size_t)y0 * 256 + cidx];
                #pragma unroll
                for (int y = y0; y < y0 + 8; y++) {
                    float d1 = cur.y - cur.x;
                    float d2 = cur.z - cur.y;
                    float d3 = cur.w - cur.z;
                    acc1 += d1 * d1 + d2 * d2 + d3 * d3;
                    if (cidx < 255) {
                        float nx = spf[(size_t)y * WW + cidx * 4 + 4];
                        float d4 = nx - cur.w;
                        acc1 += d4 * d4;
                    }
                    if (y + 1 < HH) {
                        float4 nxt = sp4[(size_t)(y + 1) * 256 + cidx];
                        float e1 = nxt.x - cur.x;
                        float e2 = nxt.y - cur.y;
                        float e3 = nxt.z - cur.z;
                        float e4 = nxt.w - cur.w;
                        acc2 += e1 * e1 + e2 * e2 + e3 * e3 + e4 * e4;
                        cur = nxt;
                    }
                }
            }
        }
    }

    // ---------------- block reduction + global accumulate ----------------
    #pragma unroll
    for (int off = 16; off; off >>= 1) {
        acc0 += __shfl_down_sync(full, acc0, off);
        acc1 += __shfl_down_sync(full, acc1, off);
        acc2 += __shfl_down_sync(full, acc2, off);
    }
    if (lane == 0) {
        const int wi = tid >> 5;
        red[0][wi] = acc0;
        red[1][wi] = acc1;
        red[2][wi] = acc2;
    }
    __syncthreads();
    if (tid == 0) {
        float a0 = 0.f, a1 = 0.f, a2 = 0.f;
        #pragma unroll
        for (int wi = 0; wi < NT / 32; wi++) {
            a0 += red[0][wi]; a1 += red[1][wi]; a2 += red[2][wi];
        }
        atomicAdd(&g_acc[0], (double)a0);
        atomicAdd(&g_acc[1], (double)a1);
        atomicAdd(&g_acc[2], (double)a2);
        __threadfence();
        unsigned old = atomicAdd(&g_count, 1u);
        if (old == GRID_BLOCKS - 1) {
            __threadfence();
            volatile double* ga = g_acc;
            double c  = ga[0];
            double xs = ga[1];
            double ys = ga[2];
            double nccl = -c / ((double)BB * HH * WW);
            double mdx  = xs / ((double)BB * 2.0 * HH * (WW - 1));
            double mdy  = ys / ((double)BB * 2.0 * (HH - 1) * WW);
            double sml  = (mdx + mdy) * 0.5 * 0.01;
            out[0] = (float)(nccl + sml);
            out[1] = (float)nccl;
            out[2] = (float)sml;
            ga[0] = 0.0; ga[1] = 0.0; ga[2] = 0.0;
            atomicExch(&g_ticket, 0u);
            __threadfence();
            atomicExch(&g_count, 0u);
        }
    }
}

extern "C" void kernel_launch(void* const* d_in, const int* in_sizes, int n_in,
                              void* d_out, int out_size)
{
    const float* I = (const float*)d_in[0];
    const float* J = (const float*)d_in[1];
    const float* s = (const float*)d_in[2];
    // d_in[3] = sum_filt (all-ones 9x9) is baked into the math
    float* out = (float*)d_out;

    fused_kernel<<<GRID_BLOCKS, NT>>>(I, J, s, out);
}

// round 15
// speedup vs baseline: 1.2454x; 1.2454x over previous
#include <cuda_runtime.h>

#define BB 8
#define HH 1024
#define WW 1024
#define NT 256

// ---- NCC warp tasks: float4-per-lane (4 cols/lane, 120 outputs/warp-row) ----
#define OUTW 120
#define NSTRIP 9
#define SEG 16
#define VSEG (HH / SEG)                 // 64
#define NCC_TASKS (NSTRIP * VSEG * BB)  // 4608

// ---- smoothness warp tasks: 8-row full-width strips ----
#define SM_TASKS 2048                   // 16 planes x 128 strips
#define NTASKS (NCC_TASKS + SM_TASKS)   // 6656

#define GRID_BLOCKS 592                 // 4/SM x 148 SMs

typedef unsigned long long u64;

__device__ double g_acc[3] = {0.0, 0.0, 0.0};
__device__ unsigned int g_ticket = 0;
__device__ unsigned int g_count = 0;

__device__ __forceinline__ float frcp(float x) {
    float r; asm("rcp.approx.ftz.f32 %0, %1;" : "=f"(r) : "f"(x)); return r;
}
__device__ __forceinline__ u64 PK2(float lo, float hi) {
    u64 r; asm("mov.b64 %0, {%1, %2};" : "=l"(r) : "f"(lo), "f"(hi)); return r;
}
__device__ __forceinline__ void UPK2(u64 v, float& lo, float& hi) {
    asm("mov.b64 {%0, %1}, %2;" : "=f"(lo), "=f"(hi) : "l"(v));
}
__device__ __forceinline__ u64 ADD2(u64 a, u64 b) {
    u64 r; asm("add.rn.f32x2 %0, %1, %2;" : "=l"(r) : "l"(a), "l"(b)); return r;
}
__device__ __forceinline__ u64 MUL2(u64 a, u64 b) {
    u64 r; asm("mul.rn.f32x2 %0, %1, %2;" : "=l"(r) : "l"(a), "l"(b)); return r;
}
__device__ __forceinline__ u64 FMA2(u64 a, u64 b, u64 c) {
    u64 r; asm("fma.rn.f32x2 %0, %1, %2, %3;" : "=l"(r) : "l"(a), "l"(b), "l"(c)); return r;
}

// Horizontal 9-tap window sums for a lane owning cols rb..rb+3.
// All 8 shuffles independent (depth-1). Valid for lanes 1..30.
__device__ __forceinline__ void hwin4(float v0, float v1, float v2, float v3,
                                      float& W0, float& W1, float& W2, float& W3) {
    const unsigned m = 0xffffffffu;
    float p2 = v0 + v1;
    float s2 = v2 + v3;
    float Q  = p2 + s2;
    float p3 = p2 + v2;
    float s3 = s2 + v1;
    float Qm  = __shfl_up_sync(m, Q, 1);
    float s3m = __shfl_up_sync(m, s3, 1);
    float s2m = __shfl_up_sync(m, s2, 1);
    float s1m = __shfl_up_sync(m, v3, 1);
    float p1p = __shfl_down_sync(m, v0, 1);
    float p2p = __shfl_down_sync(m, p2, 1);
    float p3p = __shfl_down_sync(m, p3, 1);
    float Qp  = __shfl_down_sync(m, Q, 1);
    W0 = Qm  + Q + p1p;
    W1 = s3m + Q + p2p;
    W2 = s2m + Q + p3p;
    W3 = s1m + Q + Qp;
}

template<bool MASKED, bool YCLEAN>
__device__ __forceinline__ float ncc_task(const float4* __restrict__ Ip,
                                          const float4* __restrict__ Jp,
                                          int y0, u64 cm01, u64 cm23,
                                          bool m0, bool m1, bool m2, bool m3)
{
    const int RS = WW / 4;
    const float4 z4 = make_float4(0.f, 0.f, 0.f, 0.f);
    const u64 NEG1   = PK2(-1.0f, -1.0f);
    const u64 NINV81 = PK2(-1.0f / 81.0f, -1.0f / 81.0f);
    const u64 EPS2   = PK2(1e-9f, 1e-9f);

    u64 sI01=0, sI23=0, sJ01=0, sJ23=0;
    u64 sII01=0, sII23=0, sJJ01=0, sJJ23=0, sIJ01=0, sIJ23=0;

    // prefill rows y0-5 .. y0+3 -> invariant: sums = rows y-5..y+3 at loop top
    #pragma unroll
    for (int k = 0; k < 9; k++) {
        const int y = y0 - 5 + k;
        const bool ok = YCLEAN || (y >= 0);
        float4 vi = ok ? Ip[(long)y * RS] : z4;
        float4 vj = ok ? Jp[(long)y * RS] : z4;
        u64 i01 = PK2(vi.x, vi.y), i23 = PK2(vi.z, vi.w);
        u64 j01 = PK2(vj.x, vj.y), j23 = PK2(vj.z, vj.w);
        if (MASKED) {
            i01 = MUL2(i01, cm01); i23 = MUL2(i23, cm23);
            j01 = MUL2(j01, cm01); j23 = MUL2(j23, cm23);
        }
        sI01 = ADD2(sI01, i01);   sI23 = ADD2(sI23, i23);
        sJ01 = ADD2(sJ01, j01);   sJ23 = ADD2(sJ23, j23);
        sII01 = FMA2(i01, i01, sII01); sII23 = FMA2(i23, i23, sII23);
        sJJ01 = FMA2(j01, j01, sJJ01); sJJ23 = FMA2(j23, j23, sJJ23);
        sIJ01 = FMA2(i01, j01, sIJ01); sIJ23 = FMA2(i23, j23, sIJ23);
    }

    // single stream base at row y0+4; old rows addressed via immediate -9-row offset
    const float4* pIn = Ip + (long)(y0 + 4) * RS;
    const float4* pJn = Jp + (long)(y0 + 4) * RS;
    const int ylim = HH - 4 - y0;

    float ccSum = 0.f;

    #pragma unroll 4
    for (int u = 0; u < SEG; u++) {
        float4 vN_i, vN_j, vO_i, vO_j;
        if (YCLEAN) {
            vN_i = pIn[(long)u * RS];
            vN_j = pJn[(long)u * RS];
            vO_i = pIn[(long)(u - 9) * RS];
            vO_j = pJn[(long)(u - 9) * RS];
        } else {
            const bool okn = u < ylim;
            const bool oko = (y0 + u - 5) >= 0;
            vN_i = okn ? pIn[(long)u * RS] : z4;
            vN_j = okn ? pJn[(long)u * RS] : z4;
            vO_i = oko ? pIn[(long)(u - 9) * RS] : z4;
            vO_j = oko ? pJn[(long)(u - 9) * RS] : z4;
        }
        u64 iN01 = PK2(vN_i.x, vN_i.y), iN23 = PK2(vN_i.z, vN_i.w);
        u64 jN01 = PK2(vN_j.x, vN_j.y), jN23 = PK2(vN_j.z, vN_j.w);
        u64 iO01 = PK2(vO_i.x, vO_i.y), iO23 = PK2(vO_i.z, vO_i.w);
        u64 jO01 = PK2(vO_j.x, vO_j.y), jO23 = PK2(vO_j.z, vO_j.w);
        if (MASKED) {
            iN01 = MUL2(iN01, cm01); iN23 = MUL2(iN23, cm23);
            jN01 = MUL2(jN01, cm01); jN23 = MUL2(jN23, cm23);
            iO01 = MUL2(iO01, cm01); iO23 = MUL2(iO23, cm23);
            jO01 = MUL2(jO01, cm01); jO23 = MUL2(jO23, cm23);
        }

        // combined slide: +row(y+4) -row(y-5)  => window rows y-4..y+4
        u64 dI01 = FMA2(iO01, NEG1, iN01), dI23 = FMA2(iO23, NEG1, iN23);
        u64 dJ01 = FMA2(jO01, NEG1, jN01), dJ23 = FMA2(jO23, NEG1, jN23);
        u64 eI01 = ADD2(iN01, iO01),       eI23 = ADD2(iN23, iO23);
        u64 eJ01 = ADD2(jN01, jO01),       eJ23 = ADD2(jN23, jO23);
        sI01 = ADD2(sI01, dI01);  sI23 = ADD2(sI23, dI23);
        sJ01 = ADD2(sJ01, dJ01);  sJ23 = ADD2(sJ23, dJ23);
        sII01 = FMA2(dI01, eI01, sII01); sII23 = FMA2(dI23, eI23, sII23);
        sJJ01 = FMA2(dJ01, eJ01, sJJ01); sJJ23 = FMA2(dJ23, eJ23, sJJ23);
        sIJ01 = FMA2(dI01, jN01, sIJ01); sIJ01 = FMA2(iO01, dJ01, sIJ01);
        sIJ23 = FMA2(dI23, jN23, sIJ23); sIJ23 = FMA2(iO23, dJ23, sIJ23);

        // unpack vertical sums for the shuffle-based horizontal pass
        float aI0,aI1,aI2,aI3, aJ0,aJ1,aJ2,aJ3;
        float aII0,aII1,aII2,aII3, aJJ0,aJJ1,aJJ2,aJJ3, aIJ0,aIJ1,aIJ2,aIJ3;
        UPK2(sI01,  aI0,  aI1);  UPK2(sI23,  aI2,  aI3);
        UPK2(sJ01,  aJ0,  aJ1);  UPK2(sJ23,  aJ2,  aJ3);
        UPK2(sII01, aII0, aII1); UPK2(sII23, aII2, aII3);
        UPK2(sJJ01, aJJ0, aJJ1); UPK2(sJJ23, aJJ2, aJJ3);
        UPK2(sIJ01, aIJ0, aIJ1); UPK2(sIJ23, aIJ2, aIJ3);

        float TI0,TI1,TI2,TI3, TJ0,TJ1,TJ2,TJ3;
        float TII0,TII1,TII2,TII3, TJJ0,TJJ1,TJJ2,TJJ3, TIJ0,TIJ1,TIJ2,TIJ3;
        hwin4(aI0,  aI1,  aI2,  aI3,  TI0,  TI1,  TI2,  TI3);
        hwin4(aJ0,  aJ1,  aJ2,  aJ3,  TJ0,  TJ1,  TJ2,  TJ3);
        hwin4(aII0, aII1, aII2, aII3, TII0, TII1, TII2, TII3);
        hwin4(aJJ0, aJJ1, aJJ2, aJJ3, TJJ0, TJJ1, TJJ2, TJJ3);
        hwin4(aIJ0, aIJ1, aIJ2, aIJ3, TIJ0, TIJ1, TIJ2, TIJ3);

        // packed cc epilogue for column pairs (0,1) and (2,3)
        {
            u64 TI = PK2(TI0, TI1), TJ = PK2(TJ0, TJ1);
            u64 t  = MUL2(TI, NINV81);
            u64 cr = FMA2(t, TJ, PK2(TIJ0, TIJ1));
            u64 iv = FMA2(t, TI, PK2(TII0, TII1));
            u64 q  = MUL2(TJ, NINV81);
            u64 jv = FMA2(q, TJ, PK2(TJJ0, TJJ1));
            u64 den = FMA2(iv, jv, EPS2);
            u64 c2  = MUL2(cr, cr);
            float d0, d1, n0, n1;
            UPK2(den, d0, d1); UPK2(c2, n0, n1);
            if (m0) ccSum += n0 * frcp(d0);
            if (m1) ccSum += n1 * frcp(d1);
        }
        {
            u64 TI = PK2(TI2, TI3), TJ = PK2(TJ2, TJ3);
            u64 t  = MUL2(TI, NINV81);
            u64 cr = FMA2(t, TJ, PK2(TIJ2, TIJ3));
            u64 iv = FMA2(t, TI, PK2(TII2, TII3));
            u64 q  = MUL2(TJ, NINV81);
            u64 jv = FMA2(q, TJ, PK2(TJJ2, TJJ3));
            u64 den = FMA2(iv, jv, EPS2);
            u64 c2  = MUL2(cr, cr);
            float d0, d1, n0, n1;
            UPK2(den, d0, d1); UPK2(c2, n0, n1);
            if (m2) ccSum += n0 * frcp(d0);
            if (m3) ccSum += n1 * frcp(d1);
        }
    }
    return ccSum;
}

__global__ __launch_bounds__(NT, 4)
void fused_kernel(const float* __restrict__ I,
                  const float* __restrict__ J,
                  const float* __restrict__ S,
                  float* __restrict__ out)
{
    __shared__ float red[3][NT / 32];
    const int tid  = threadIdx.x;
    const int lane = tid & 31;
    const unsigned full = 0xffffffffu;

    float acc0 = 0.f, acc1 = 0.f, acc2 = 0.f;

    for (;;) {
        unsigned t;
        if (lane == 0) t = atomicAdd(&g_ticket, 1u);
        t = __shfl_sync(full, t, 0);
        if (t >= NTASKS) break;

        if (t < NCC_TASKS) {
            // v varies fastest -> adjacent tickets share halo rows (L2 locality)
            const int v  = t % VSEG;
            const int rr = t / VSEG;
            const int s  = rr % NSTRIP;
            const int b  = rr / NSTRIP;

            const int rb = s * OUTW - 4 + 4 * lane;
            int rbc = rb < 0 ? 0 : (rb > (WW - 4) ? (WW - 4) : rb);

            const float4* Ip = (const float4*)(I + (size_t)b * HH * WW + rbc);
            const float4* Jp = (const float4*)(J + (size_t)b * HH * WW + rbc);

            const float c0 = ((unsigned)(rb + 0) < (unsigned)WW) ? 1.f : 0.f;
            const float c1 = ((unsigned)(rb + 1) < (unsigned)WW) ? 1.f : 0.f;
            const float c2 = ((unsigned)(rb + 2) < (unsigned)WW) ? 1.f : 0.f;
            const float c3 = ((unsigned)(rb + 3) < (unsigned)WW) ? 1.f : 0.f;
            const u64 cm01 = PK2(c0, c1);
            const u64 cm23 = PK2(c2, c3);

            const bool lmid = (lane >= 1) && (lane <= 30);
            const bool m0 = lmid && (rb + 0 < WW);
            const bool m1 = lmid && (rb + 1 < WW);
            const bool m2 = lmid && (rb + 2 < WW);
            const bool m3 = lmid && (rb + 3 < WW);
            const int y0 = v * SEG;

            const bool colclean = __all_sync(full, (unsigned)rb < (unsigned)(WW - 3));
            const bool yclean   = (y0 >= 5) && (y0 + SEG + 4 <= HH);

            if (colclean) {
                acc0 += yclean ? ncc_task<false, true >(Ip, Jp, y0, cm01, cm23, m0, m1, m2, m3)
                               : ncc_task<false, false>(Ip, Jp, y0, cm01, cm23, m0, m1, m2, m3);
            } else {
                acc0 += yclean ? ncc_task<true,  true >(Ip, Jp, y0, cm01, cm23, m0, m1, m2, m3)
                               : ncc_task<true,  false>(Ip, Jp, y0, cm01, cm23, m0, m1, m2, m3);
            }
        } else {
            // ------------- smoothness: 8-row strip -------------
            const unsigned n = t - NCC_TASKS;
            const int plane = n >> 7;
            const int strip = n & 127;
            const float*  spf = S + (size_t)plane * HH * WW;
            const float4* sp4 = (const float4*)spf;
            const int y0 = strip * 8;

            #pragma unroll 1
            for (int p = 0; p < 8; p++) {
                const int cidx = p * 32 + lane;
                float4 cur = sp4[(size_t)y0 * 256 + cidx];
                #pragma unroll
                for (int y = y0; y < y0 + 8; y++) {
                    float d1 = cur.y - cur.x;
                    float d2 = cur.z - cur.y;
                    float d3 = cur.w - cur.z;
                    acc1 += d1 * d1 + d2 * d2 + d3 * d3;
                    if (cidx < 255) {
                        float nx = spf[(size_t)y * WW + cidx * 4 + 4];
                        float d4 = nx - cur.w;
                        acc1 += d4 * d4;
                    }
                    if (y + 1 < HH) {
                        float4 nxt = sp4[(size_t)(y + 1) * 256 + cidx];
                        float e1 = nxt.x - cur.x;
                        float e2 = nxt.y - cur.y;
                        float e3 = nxt.z - cur.z;
                        float e4 = nxt.w - cur.w;
                        acc2 += e1 * e1 + e2 * e2 + e3 * e3 + e4 * e4;
                        cur = nxt;
                    }
                }
            }
        }
    }

    // ---------------- block reduction + global accumulate ----------------
    #pragma unroll
    for (int off = 16; off; off >>= 1) {
        acc0 += __shfl_down_sync(full, acc0, off);
        acc1 += __shfl_down_sync(full, acc1, off);
        acc2 += __shfl_down_sync(full, acc2, off);
    }
    if (lane == 0) {
        const int wi = tid >> 5;
        red[0][wi] = acc0;
        red[1][wi] = acc1;
        red[2][wi] = acc2;
    }
    __syncthreads();
    if (tid == 0) {
        float a0 = 0.f, a1 = 0.f, a2 = 0.f;
        #pragma unroll
        for (int wi = 0; wi < NT / 32; wi++) {
            a0 += red[0][wi]; a1 += red[1][wi]; a2 += red[2][wi];
        }
        atomicAdd(&g_acc[0], (double)a0);
        atomicAdd(&g_acc[1], (double)a1);
        atomicAdd(&g_acc[2], (double)a2);
        __threadfence();
        unsigned old = atomicAdd(&g_count, 1u);
        if (old == GRID_BLOCKS - 1) {
            __threadfence();
            volatile double* ga = g_acc;
            double c  = ga[0];
            double xs = ga[1];
            double ys = ga[2];
            double nccl = -c / ((double)BB * HH * WW);
            double mdx  = xs / ((double)BB * 2.0 * HH * (WW - 1));
            double mdy  = ys / ((double)BB * 2.0 * (HH - 1) * WW);
            double sml  = (mdx + mdy) * 0.5 * 0.01;
            out[0] = (float)(nccl + sml);
            out[1] = (float)nccl;
            out[2] = (float)sml;
            ga[0] = 0.0; ga[1] = 0.0; ga[2] = 0.0;
            atomicExch(&g_ticket, 0u);
            __threadfence();
            atomicExch(&g_count, 0u);
        }
    }
}

extern "C" void kernel_launch(void* const* d_in, const int* in_sizes, int n_in,
                              void* d_out, int out_size)
{
    const float* I = (const float*)d_in[0];
    const float* J = (const float*)d_in[1];
    const float* s = (const float*)d_in[2];
    // d_in[3] = sum_filt (all-ones 9x9) is baked into the math
    float* out = (float*)d_out;

    fused_kernel<<<GRID_BLOCKS, NT>>>(I, J, s, out);
}